// round 16
// baseline (speedup 1.0000x reference)
#include <cuda_runtime.h>
#include <math.h>

#define B_ 4096
#define T_ 40
#define BT_ (B_*T_)
#define G_ 14
#define NCTA ((B_ + 2*G_ - 1)/(2*G_))   /* 147 */

__device__ float g_base1[B_*128];

// ---------- packed f32x2 helpers ----------
__device__ __forceinline__ unsigned long long pk2(float lo, float hi){
    return ((unsigned long long)__float_as_uint(hi) << 32) | (unsigned long long)__float_as_uint(lo);
}
__device__ __forceinline__ unsigned long long fma2(unsigned long long a, unsigned long long b, unsigned long long c){
    unsigned long long d;
    asm("fma.rn.f32x2 %0, %1, %2, %3;" : "=l"(d) : "l"(a), "l"(b), "l"(c));
    return d;
}
__device__ __forceinline__ unsigned long long add2(unsigned long long a, unsigned long long b){
    unsigned long long d;
    asm("add.rn.f32x2 %0, %1, %2;" : "=l"(d) : "l"(a), "l"(b));
    return d;
}
__device__ __forceinline__ float red2(unsigned long long a){
    float lo = __uint_as_float((unsigned)(a & 0xffffffffULL));
    float hi = __uint_as_float((unsigned)(a >> 32));
    return lo + hi;
}

// half-dot over 64 floats (this thread's khalf), interleaved 16B chunks.
// khalf 0 reads bytes [32*i, 32*i+16), khalf 1 reads [32*i+16, 32*i+32).
__device__ __forceinline__ float matvec64(const unsigned long long* w, const float* hbuf, int khalf){
    unsigned long long a0=0ULL,a1=0ULL,a2=0ULL,a3=0ULL;
    const ulonglong2* hp = reinterpret_cast<const ulonglong2*>(hbuf + khalf*4);
    #pragma unroll
    for (int i=0;i<16;i+=2){
        ulonglong2 p = hp[2*i];        // hbuf + i*8 + khalf*4 floats
        a0 = fma2(p.x, w[2*i+0], a0);
        a1 = fma2(p.y, w[2*i+1], a1);
        ulonglong2 q = hp[2*(i+1)];
        a2 = fma2(q.x, w[2*i+2], a2);
        a3 = fma2(q.y, w[2*i+3], a3);
    }
    return red2(add2(add2(a0,a1), add2(a2,a3)));
}

// ---------- base1 precompute: base1 = [pb, eh] @ W1[0:192] + b1 ----------
__global__ void base1_kernel(const float* __restrict__ pb, const float* __restrict__ eh,
                             const float* __restrict__ W1, const float* __restrict__ b1){
    __shared__ float sin_[16][192];
    const int jj = threadIdx.x;
    const int r0 = blockIdx.x * 16;
    for (int r=0;r<16;r++){
        for (int k=jj; k<192; k+=128){
            sin_[r][k] = (k < 64) ? pb[(size_t)(r0+r)*64 + k]
                                  : eh[(size_t)(r0+r)*128 + (k-64)];
        }
    }
    __syncthreads();
    float acc[16];
    const float bb = b1[jj];
    #pragma unroll
    for (int r=0;r<16;r++) acc[r]=bb;
    for (int k=0;k<192;k++){
        float wv = W1[k*128+jj];
        #pragma unroll
        for (int r=0;r<16;r++) acc[r] = fmaf(sin_[r][k], wv, acc[r]);
    }
    #pragma unroll
    for (int r=0;r<16;r++) g_base1[(size_t)(r0+r)*128 + jj] = acc[r];
}

// ---------- main persistent rollout kernel (512 threads) ----------
__global__ void __launch_bounds__(512,1) rollout_kernel(
    const float* __restrict__ idm_params,
    const float* __restrict__ idm_s,
    const float* __restrict__ mcs,
    const float* __restrict__ W1,
    const float* __restrict__ W2,
    const float* __restrict__ b2,
    const float* __restrict__ W3,
    const float* __restrict__ b3,
    const float* __restrict__ Wf,
    const float* __restrict__ bf,
    const float* __restrict__ Wm,
    const float* __restrict__ bm,
    const float* __restrict__ smean,
    const float* __restrict__ svar,
    float* __restrict__ out)
{
    __shared__ __align__(16) float h1s[2][G_][128];
    __shared__ __align__(16) float h2s[2][G_][128];
    __shared__ __align__(16) float base_s[2][G_][128];
    __shared__ float red_s[G_][16];
    __shared__ float extra_s[2][G_][9];
    __shared__ float prm_s[2][G_][5];   // invdv, tgap, jamx, mact, invdn
    __shared__ float vx_s[2][G_][2];    // v, x
    __shared__ float sc_s[12];          // m0..5, is0..5

    const int tid   = threadIdx.x;
    const int half  = tid >> 8;          // 0: W2 layer.  1: W3 layer + epilogue
    const int t2    = tid & 255;
    const int lane  = tid & 31;
    const int ww    = t2 >> 5;           // warp index within half (0..7)
    const int khalf = (lane >> 4) & 1;   // k-split half
    const int j     = (ww << 4) | (lane & 15);   // output column 0..127
    const int r0    = blockIdx.x * (2*G_);

    // weight columns: this thread covers k = 8*i + 4*khalf + {0,1,2,3}, i=0..15
    unsigned long long w[32];
    {
        const float* Wsrc = half ? W3 : W2;
        #pragma unroll
        for (int i=0;i<16;i++){
            int kb = 8*i + 4*khalf;
            w[2*i+0] = pk2(Wsrc[(kb+0)*128 + j], Wsrc[(kb+1)*128 + j]);
            w[2*i+1] = pk2(Wsrc[(kb+2)*128 + j], Wsrc[(kb+3)*128 + j]);
        }
    }
    const float bias = half ? b3[j] : b2[j];
    const float wfj = Wf[j], wmj = Wm[j];
    const float bfv = bf[0], bmv = bm[0];

    const float w1e0 = W1[192*128+j], w1e1 = W1[193*128+j], w1e2 = W1[194*128+j];
    const float w1e3 = W1[195*128+j], w1e4 = W1[196*128+j], w1e5 = W1[197*128+j];
    const float w1m0 = W1[198*128+j], w1m1 = W1[199*128+j], w1m2 = W1[200*128+j];

    if (tid < 12){
        sc_s[tid] = (tid < 6) ? smean[tid] : rsqrtf(svar[tid-6]);
    }
    // stage base1 for all 28 rows
    for (int idx = tid; idx < 2*G_*128; idx += 512){
        int grp = idx / (G_*128);
        int rem = idx - grp*(G_*128);
        int g = rem >> 7, jj = rem & 127;
        int row = r0 + grp*G_ + g; if (row >= B_) row = B_-1;
        base_s[grp][g][jj] = g_base1[(size_t)row*128 + jj];
    }
    __syncthreads();

    // per-row params/state -> smem (half2, threads t2<G_ own one row id each)
    if (half == 1 && t2 < G_){
        const float m0=sc_s[0],m1=sc_s[1],m2=sc_s[2],m3=sc_s[3],m4=sc_s[4],m5=sc_s[5];
        const float is0=sc_s[6],is1=sc_s[7],is2=sc_s[8],is3=sc_s[9],is4=sc_s[10],is5=sc_s[11];
        #pragma unroll
        for (int grp=0; grp<2; grp++){
            int row = r0 + grp*G_ + t2;
            if (row >= B_) row = B_-1;
            const float* p = idm_params + (size_t)row*5;
            prm_s[grp][t2][0] = 1.0f/p[0];
            prm_s[grp][t2][1] = p[1];
            prm_s[grp][t2][2] = p[2];
            prm_s[grp][t2][3] = p[3];
            prm_s[grp][t2][4] = 1.0f/(2.0f*sqrtf(p[3]*p[4]));
            const float* s0 = idm_s + (size_t)row*T_*11;
            float vv = s0[0], xx = s0[3];
            vx_s[grp][t2][0] = vv; vx_s[grp][t2][1] = xx;
            float fv = s0[1], mv = s0[2], fx = s0[4], mx = s0[5], mex = s0[10];
            bool  me = (mex > 0.5f);
            float edx = me ? (mx - xx) : 70.0f;
            float edv = me ? (vv - mv) : 0.0f;
            const float* mc0 = mcs + (size_t)row*T_*3;
            extra_s[grp][t2][0] = (vv - m0)*is0;
            extra_s[grp][t2][1] = (fv - m1)*is1;
            extra_s[grp][t2][2] = ((vv - fv) - m2)*is2;
            extra_s[grp][t2][3] = ((fx - xx) - m3)*is3;
            extra_s[grp][t2][4] = (edv - m4)*is4;
            extra_s[grp][t2][5] = (edx - m5)*is5;
            extra_s[grp][t2][6] = mc0[0];
            extra_s[grp][t2][7] = mc0[1];
            extra_s[grp][t2][8] = mc0[2];
        }
    }
    __syncthreads();

    auto build_h1 = [&](int grp){
        // khalf splits the g-range; lanes of each khalf cover all 128 j
        for (int g = khalf; g < G_; g += 2){
            float a = base_s[grp][g][j];
            a = fmaf(extra_s[grp][g][0], w1e0, a);
            a = fmaf(extra_s[grp][g][1], w1e1, a);
            a = fmaf(extra_s[grp][g][2], w1e2, a);
            a = fmaf(extra_s[grp][g][3], w1e3, a);
            a = fmaf(extra_s[grp][g][4], w1e4, a);
            a = fmaf(extra_s[grp][g][5], w1e5, a);
            a = fmaf(extra_s[grp][g][6], w1m0, a);
            a = fmaf(extra_s[grp][g][7], w1m1, a);
            a = fmaf(extra_s[grp][g][8], w1m2, a);
            h1s[grp][g][j] = fmaxf(a, 0.3f*a);
        }
    };

    // t=0: half1 builds h1 group A (grp0), half2 builds group B (grp1)
    build_h1(half);
    __syncthreads();

    auto mlp2 = [&](int grp){
        #pragma unroll 2
        for (int g=0; g<G_; g++){
            float part = matvec64(w, h1s[grp][g], khalf);
            float acc = part + __shfl_xor_sync(0xffffffffu, part, 16) + bias;
            if (khalf == 0) h2s[grp][g][j] = fmaxf(acc, 0.3f*acc);
        }
    };

    // prologue: h2 for group B, t=0
    if (half == 0) mlp2(1);
    __syncthreads();

    auto idm_act = [](float v, float dv, float dx,
                      float inv_desv, float tgap, float jamx, float mact, float invden)->float{
        float dxc = 0.1f + fmaxf(dx, 0.0f);
        float gap = fmaxf(fmaf(tgap, v, jamx) + v*dv*invden, 0.0f);
        float vr  = v*inv_desv; float vr2 = vr*vr;
        float gr  = gap/dxc;
        float a   = mact*(1.0f - vr2*vr2 - gr*gr);
        return fminf(fmaxf(a,-50.0f),50.0f);
    };

    auto phase2 = [&](int grp, int t){
        // prefetch per-row step data (threads t2<G_); hides under the matvecs
        float s1,s2,s4,s5,s10, n1,n2,n4,n5,n10, c0,c1,c2;
        if (t2 < G_){
            int row = r0 + grp*G_ + t2; if (row >= B_) row = B_-1;
            const float* sp = idm_s + ((size_t)row*T_ + t)*11;
            s1=sp[1]; s2=sp[2]; s4=sp[4]; s5=sp[5]; s10=sp[10];
            int tn = (t+1 < T_) ? (t+1) : (T_-1);
            const float* snp = idm_s + ((size_t)row*T_ + tn)*11;
            n1=snp[1]; n2=snp[2]; n4=snp[4]; n5=snp[5]; n10=snp[10];
            const float* mcp = mcs + ((size_t)row*T_ + tn)*3;
            c0=mcp[0]; c1=mcp[1]; c2=mcp[2];
        }
        #pragma unroll 2
        for (int g=0; g<G_; g++){
            float part = matvec64(w, h2s[grp][g], khalf);
            float acc = part + __shfl_xor_sync(0xffffffffu, part, 16) + bias;
            float h3  = fmaxf(acc, 0.3f*acc);
            // both khalf copies hold h3; warp sum = 2 * sum over this warp's 16 j
            float pf = h3*wfj, pm = h3*wmj;
            #pragma unroll
            for (int o=16;o;o>>=1){
                pf += __shfl_xor_sync(0xffffffffu, pf, o);
                pm += __shfl_xor_sync(0xffffffffu, pm, o);
            }
            if (lane==0){ red_s[g][ww] = pf; red_s[g][8+ww] = pm; }
        }
        asm volatile("bar.sync 1, 256;" ::: "memory");   // half2-only
        if (t2 < G_){
            const int r = t2;
            float lf = ((red_s[r][0]+red_s[r][1]) + (red_s[r][2]+red_s[r][3]))
                     + ((red_s[r][4]+red_s[r][5]) + (red_s[r][6]+red_s[r][7]));
            float lm = ((red_s[r][8]+red_s[r][9]) + (red_s[r][10]+red_s[r][11]))
                     + ((red_s[r][12]+red_s[r][13]) + (red_s[r][14]+red_s[r][15]));
            float d  = 5.0f*((0.5f*lf + bfv) - (0.5f*lm + bmv));
            float e  = expf(-d);
            float fatt = 1.0f/(1.0f+e);
            float matt = e*fatt;

            float ivd = prm_s[grp][r][0], tg = prm_s[grp][r][1], jx = prm_s[grp][r][2];
            float ma  = prm_s[grp][r][3], ivn = prm_s[grp][r][4];
            float vv = vx_s[grp][r][0], xx = vx_s[grp][r][1];
            bool  me = (s10 > 0.5f);
            float ef_dx = s4 - xx, ef_dv = vv - s1;
            float em_dx = me ? (s5 - xx) : 70.0f;
            float em_dv = me ? (vv - s2) : 0.0f;
            float efa = idm_act(vv, ef_dv, ef_dx, ivd, tg, jx, ma, ivn);
            float ema = idm_act(vv, em_dv, em_dx, ivd, tg, jx, ma, ivn);
            float act = fatt*efa + matt*ema;

            int row = r0 + grp*G_ + r;
            if (row < B_){
                int o = row*T_ + t;
                out[o]         = fminf(fmaxf(act,-5.4f),5.4f);
                out[BT_ + o]   = fatt;
                out[2*BT_ + o] = matt;
            }
            vv = fmaf(act, 0.1f, vv);
            xx = xx + vv*0.1f + act*0.005f;
            vx_s[grp][r][0] = vv; vx_s[grp][r][1] = xx;

            const float m0=sc_s[0],m1=sc_s[1],m2=sc_s[2],m3=sc_s[3],m4=sc_s[4],m5=sc_s[5];
            const float is0=sc_s[6],is1=sc_s[7],is2=sc_s[8],is3=sc_s[9],is4=sc_s[10],is5=sc_s[11];
            bool  men = (n10 > 0.5f);
            float edx = men ? (n5 - xx) : 70.0f;
            float edv = men ? (vv - n2) : 0.0f;
            extra_s[grp][r][0] = (vv - m0)*is0;
            extra_s[grp][r][1] = (n1 - m1)*is1;
            extra_s[grp][r][2] = ((vv - n1) - m2)*is2;
            extra_s[grp][r][3] = ((n4 - xx) - m3)*is3;
            extra_s[grp][r][4] = (edv - m4)*is4;
            extra_s[grp][r][5] = (edx - m5)*is5;
            extra_s[grp][r][6] = c0;
            extra_s[grp][r][7] = c1;
            extra_s[grp][r][8] = c2;
        }
        asm volatile("bar.sync 1, 256;" ::: "memory");
        build_h1(grp);   // h1 for next step
    };

    for (int t = 0; t < T_; t++){
        // even phase: half1 -> h2 group A(t);  half2 -> h3 + epilogue group B(t)
        if (half == 0) mlp2(0); else phase2(1, t);
        __syncthreads();
        // odd phase:  half1 -> h2 group B(t+1); half2 -> h3 + epilogue group A(t)
        if (half == 0) mlp2(1); else phase2(0, t);
        __syncthreads();
    }
}

extern "C" void kernel_launch(void* const* d_in, const int* in_sizes, int n_in,
                              void* d_out, int out_size) {
    (void)in_sizes; (void)n_in; (void)out_size;
    const float* idm_params = (const float*)d_in[0];
    const float* pb         = (const float*)d_in[1];
    const float* eh         = (const float*)d_in[2];
    const float* idm_s      = (const float*)d_in[3];
    const float* mcs        = (const float*)d_in[4];
    const float* W1         = (const float*)d_in[5];
    const float* b1         = (const float*)d_in[6];
    const float* W2         = (const float*)d_in[7];
    const float* b2         = (const float*)d_in[8];
    const float* W3         = (const float*)d_in[9];
    const float* b3         = (const float*)d_in[10];
    const float* Wf         = (const float*)d_in[11];
    const float* bf         = (const float*)d_in[12];
    const float* Wm         = (const float*)d_in[13];
    const float* bm         = (const float*)d_in[14];
    const float* smean      = (const float*)d_in[15];
    const float* svar       = (const float*)d_in[16];
    float* out = (float*)d_out;

    base1_kernel<<<B_/16, 128>>>(pb, eh, W1, b1);
    rollout_kernel<<<NCTA, 512>>>(idm_params, idm_s, mcs, W1, W2, b2, W3, b3,
                                  Wf, bf, Wm, bm, smean, svar, out);
}

// round 17
// speedup vs baseline: 1.0003x; 1.0003x over previous
#include <cuda_runtime.h>
#include <math.h>

#define B_ 4096
#define T_ 40
#define BT_ (B_*T_)
#define G_ 14
#define NCTA ((B_ + 2*G_ - 1)/(2*G_))   /* 147 */

__device__ float g_base1[B_*128];

// ---------- packed f32x2 helpers ----------
__device__ __forceinline__ unsigned long long pk2(float lo, float hi){
    return ((unsigned long long)__float_as_uint(hi) << 32) | (unsigned long long)__float_as_uint(lo);
}
__device__ __forceinline__ unsigned long long fma2(unsigned long long a, unsigned long long b, unsigned long long c){
    unsigned long long d;
    asm("fma.rn.f32x2 %0, %1, %2, %3;" : "=l"(d) : "l"(a), "l"(b), "l"(c));
    return d;
}
__device__ __forceinline__ unsigned long long add2(unsigned long long a, unsigned long long b){
    unsigned long long d;
    asm("add.rn.f32x2 %0, %1, %2;" : "=l"(d) : "l"(a), "l"(b));
    return d;
}
__device__ __forceinline__ float red2(unsigned long long a){
    float lo = __uint_as_float((unsigned)(a & 0xffffffffULL));
    float hi = __uint_as_float((unsigned)(a >> 32));
    return lo + hi;
}

// half-dot over 64 floats (this thread's khalf), interleaved 16B chunks.
// khalf 0 reads bytes [32*i, 32*i+16), khalf 1 reads [32*i+16, 32*i+32).
__device__ __forceinline__ float matvec64(const unsigned long long* w, const float* hbuf, int khalf){
    unsigned long long a0=0ULL,a1=0ULL,a2=0ULL,a3=0ULL;
    const ulonglong2* hp = reinterpret_cast<const ulonglong2*>(hbuf + khalf*4);
    #pragma unroll
    for (int i=0;i<16;i+=2){
        ulonglong2 p = hp[2*i];        // hbuf + i*8 + khalf*4 floats
        a0 = fma2(p.x, w[2*i+0], a0);
        a1 = fma2(p.y, w[2*i+1], a1);
        ulonglong2 q = hp[2*(i+1)];
        a2 = fma2(q.x, w[2*i+2], a2);
        a3 = fma2(q.y, w[2*i+3], a3);
    }
    return red2(add2(add2(a0,a1), add2(a2,a3)));
}

// ---------- base1 precompute: base1 = [pb, eh] @ W1[0:192] + b1 ----------
__global__ void base1_kernel(const float* __restrict__ pb, const float* __restrict__ eh,
                             const float* __restrict__ W1, const float* __restrict__ b1){
    __shared__ float sin_[16][192];
    const int jj = threadIdx.x;
    const int r0 = blockIdx.x * 16;
    for (int r=0;r<16;r++){
        for (int k=jj; k<192; k+=128){
            sin_[r][k] = (k < 64) ? pb[(size_t)(r0+r)*64 + k]
                                  : eh[(size_t)(r0+r)*128 + (k-64)];
        }
    }
    __syncthreads();
    float acc[16];
    const float bb = b1[jj];
    #pragma unroll
    for (int r=0;r<16;r++) acc[r]=bb;
    for (int k=0;k<192;k++){
        float wv = W1[k*128+jj];
        #pragma unroll
        for (int r=0;r<16;r++) acc[r] = fmaf(sin_[r][k], wv, acc[r]);
    }
    #pragma unroll
    for (int r=0;r<16;r++) g_base1[(size_t)(r0+r)*128 + jj] = acc[r];
}

// ---------- main persistent rollout kernel (512 threads) ----------
__global__ void __launch_bounds__(512,1) rollout_kernel(
    const float* __restrict__ idm_params,
    const float* __restrict__ idm_s,
    const float* __restrict__ mcs,
    const float* __restrict__ W1,
    const float* __restrict__ W2,
    const float* __restrict__ b2,
    const float* __restrict__ W3,
    const float* __restrict__ b3,
    const float* __restrict__ Wf,
    const float* __restrict__ bf,
    const float* __restrict__ Wm,
    const float* __restrict__ bm,
    const float* __restrict__ smean,
    const float* __restrict__ svar,
    float* __restrict__ out)
{
    __shared__ __align__(16) float h1s[2][G_][128];
    __shared__ __align__(16) float h2s[2][G_][128];
    __shared__ __align__(16) float base_s[2][G_][128];
    __shared__ float red_s[G_][16];
    __shared__ float extra_s[2][G_][9];
    __shared__ float prm_s[2][G_][5];   // invdv, tgap, jamx, mact, invdn
    __shared__ float vx_s[2][G_][2];    // v, x
    __shared__ float sc_s[12];          // m0..5, is0..5

    const int tid   = threadIdx.x;
    const int half  = tid >> 8;          // 0: W2 layer.  1: W3 layer + epilogue
    const int t2    = tid & 255;
    const int lane  = tid & 31;
    const int ww    = t2 >> 5;           // warp index within half (0..7)
    const int khalf = (lane >> 4) & 1;   // k-split half
    const int j     = (ww << 4) | (lane & 15);   // output column 0..127
    const int r0    = blockIdx.x * (2*G_);

    // weight columns: this thread covers k = 8*i + 4*khalf + {0,1,2,3}, i=0..15
    unsigned long long w[32];
    {
        const float* Wsrc = half ? W3 : W2;
        #pragma unroll
        for (int i=0;i<16;i++){
            int kb = 8*i + 4*khalf;
            w[2*i+0] = pk2(Wsrc[(kb+0)*128 + j], Wsrc[(kb+1)*128 + j]);
            w[2*i+1] = pk2(Wsrc[(kb+2)*128 + j], Wsrc[(kb+3)*128 + j]);
        }
    }
    const float bias = half ? b3[j] : b2[j];
    const float wfj = Wf[j], wmj = Wm[j];
    const float bfv = bf[0], bmv = bm[0];

    const float w1e0 = W1[192*128+j], w1e1 = W1[193*128+j], w1e2 = W1[194*128+j];
    const float w1e3 = W1[195*128+j], w1e4 = W1[196*128+j], w1e5 = W1[197*128+j];
    const float w1m0 = W1[198*128+j], w1m1 = W1[199*128+j], w1m2 = W1[200*128+j];

    if (tid < 12){
        sc_s[tid] = (tid < 6) ? smean[tid] : rsqrtf(svar[tid-6]);
    }
    // stage base1 for all 28 rows
    for (int idx = tid; idx < 2*G_*128; idx += 512){
        int grp = idx / (G_*128);
        int rem = idx - grp*(G_*128);
        int g = rem >> 7, jj = rem & 127;
        int row = r0 + grp*G_ + g; if (row >= B_) row = B_-1;
        base_s[grp][g][jj] = g_base1[(size_t)row*128 + jj];
    }
    __syncthreads();

    // per-row params/state -> smem (half2, threads t2<G_ own one row id each)
    if (half == 1 && t2 < G_){
        const float m0=sc_s[0],m1=sc_s[1],m2=sc_s[2],m3=sc_s[3],m4=sc_s[4],m5=sc_s[5];
        const float is0=sc_s[6],is1=sc_s[7],is2=sc_s[8],is3=sc_s[9],is4=sc_s[10],is5=sc_s[11];
        #pragma unroll
        for (int grp=0; grp<2; grp++){
            int row = r0 + grp*G_ + t2;
            if (row >= B_) row = B_-1;
            const float* p = idm_params + (size_t)row*5;
            prm_s[grp][t2][0] = 1.0f/p[0];
            prm_s[grp][t2][1] = p[1];
            prm_s[grp][t2][2] = p[2];
            prm_s[grp][t2][3] = p[3];
            prm_s[grp][t2][4] = 1.0f/(2.0f*sqrtf(p[3]*p[4]));
            const float* s0 = idm_s + (size_t)row*T_*11;
            float vv = s0[0], xx = s0[3];
            vx_s[grp][t2][0] = vv; vx_s[grp][t2][1] = xx;
            float fv = s0[1], mv = s0[2], fx = s0[4], mx = s0[5], mex = s0[10];
            bool  me = (mex > 0.5f);
            float edx = me ? (mx - xx) : 70.0f;
            float edv = me ? (vv - mv) : 0.0f;
            const float* mc0 = mcs + (size_t)row*T_*3;
            extra_s[grp][t2][0] = (vv - m0)*is0;
            extra_s[grp][t2][1] = (fv - m1)*is1;
            extra_s[grp][t2][2] = ((vv - fv) - m2)*is2;
            extra_s[grp][t2][3] = ((fx - xx) - m3)*is3;
            extra_s[grp][t2][4] = (edv - m4)*is4;
            extra_s[grp][t2][5] = (edx - m5)*is5;
            extra_s[grp][t2][6] = mc0[0];
            extra_s[grp][t2][7] = mc0[1];
            extra_s[grp][t2][8] = mc0[2];
        }
    }
    __syncthreads();

    auto build_h1 = [&](int grp){
        // khalf splits the g-range; lanes of each khalf cover all 128 j
        for (int g = khalf; g < G_; g += 2){
            float a = base_s[grp][g][j];
            a = fmaf(extra_s[grp][g][0], w1e0, a);
            a = fmaf(extra_s[grp][g][1], w1e1, a);
            a = fmaf(extra_s[grp][g][2], w1e2, a);
            a = fmaf(extra_s[grp][g][3], w1e3, a);
            a = fmaf(extra_s[grp][g][4], w1e4, a);
            a = fmaf(extra_s[grp][g][5], w1e5, a);
            a = fmaf(extra_s[grp][g][6], w1m0, a);
            a = fmaf(extra_s[grp][g][7], w1m1, a);
            a = fmaf(extra_s[grp][g][8], w1m2, a);
            h1s[grp][g][j] = fmaxf(a, 0.3f*a);
        }
    };

    // t=0: half1 builds h1 group A (grp0), half2 builds group B (grp1)
    build_h1(half);
    __syncthreads();

    auto mlp2 = [&](int grp){
        #pragma unroll 2
        for (int g=0; g<G_; g++){
            float part = matvec64(w, h1s[grp][g], khalf);
            float acc = part + __shfl_xor_sync(0xffffffffu, part, 16) + bias;
            if (khalf == 0) h2s[grp][g][j] = fmaxf(acc, 0.3f*acc);
        }
    };

    // prologue: h2 for group B, t=0
    if (half == 0) mlp2(1);
    __syncthreads();

    auto idm_act = [](float v, float dv, float dx,
                      float inv_desv, float tgap, float jamx, float mact, float invden)->float{
        float dxc = 0.1f + fmaxf(dx, 0.0f);
        float gap = fmaxf(fmaf(tgap, v, jamx) + v*dv*invden, 0.0f);
        float vr  = v*inv_desv; float vr2 = vr*vr;
        float gr  = gap/dxc;
        float a   = mact*(1.0f - vr2*vr2 - gr*gr);
        return fminf(fmaxf(a,-50.0f),50.0f);
    };

    auto phase2 = [&](int grp, int t){
        // prefetch per-row step data (threads t2<G_); hides under the matvecs
        float s1,s2,s4,s5,s10, n1,n2,n4,n5,n10, c0,c1,c2;
        if (t2 < G_){
            int row = r0 + grp*G_ + t2; if (row >= B_) row = B_-1;
            const float* sp = idm_s + ((size_t)row*T_ + t)*11;
            s1=sp[1]; s2=sp[2]; s4=sp[4]; s5=sp[5]; s10=sp[10];
            int tn = (t+1 < T_) ? (t+1) : (T_-1);
            const float* snp = idm_s + ((size_t)row*T_ + tn)*11;
            n1=snp[1]; n2=snp[2]; n4=snp[4]; n5=snp[5]; n10=snp[10];
            const float* mcp = mcs + ((size_t)row*T_ + tn)*3;
            c0=mcp[0]; c1=mcp[1]; c2=mcp[2];
        }
        #pragma unroll 2
        for (int g=0; g<G_; g++){
            float part = matvec64(w, h2s[grp][g], khalf);
            float acc = part + __shfl_xor_sync(0xffffffffu, part, 16) + bias;
            float h3  = fmaxf(acc, 0.3f*acc);
            // both khalf copies hold h3; warp sum = 2 * sum over this warp's 16 j
            float pf = h3*wfj, pm = h3*wmj;
            #pragma unroll
            for (int o=16;o;o>>=1){
                pf += __shfl_xor_sync(0xffffffffu, pf, o);
                pm += __shfl_xor_sync(0xffffffffu, pm, o);
            }
            if (lane==0){ red_s[g][ww] = pf; red_s[g][8+ww] = pm; }
        }
        asm volatile("bar.sync 1, 256;" ::: "memory");   // half2-only
        if (t2 < G_){
            const int r = t2;
            float lf = ((red_s[r][0]+red_s[r][1]) + (red_s[r][2]+red_s[r][3]))
                     + ((red_s[r][4]+red_s[r][5]) + (red_s[r][6]+red_s[r][7]));
            float lm = ((red_s[r][8]+red_s[r][9]) + (red_s[r][10]+red_s[r][11]))
                     + ((red_s[r][12]+red_s[r][13]) + (red_s[r][14]+red_s[r][15]));
            float d  = 5.0f*((0.5f*lf + bfv) - (0.5f*lm + bmv));
            float e  = expf(-d);
            float fatt = 1.0f/(1.0f+e);
            float matt = e*fatt;

            float ivd = prm_s[grp][r][0], tg = prm_s[grp][r][1], jx = prm_s[grp][r][2];
            float ma  = prm_s[grp][r][3], ivn = prm_s[grp][r][4];
            float vv = vx_s[grp][r][0], xx = vx_s[grp][r][1];
            bool  me = (s10 > 0.5f);
            float ef_dx = s4 - xx, ef_dv = vv - s1;
            float em_dx = me ? (s5 - xx) : 70.0f;
            float em_dv = me ? (vv - s2) : 0.0f;
            float efa = idm_act(vv, ef_dv, ef_dx, ivd, tg, jx, ma, ivn);
            float ema = idm_act(vv, em_dv, em_dx, ivd, tg, jx, ma, ivn);
            float act = fatt*efa + matt*ema;

            int row = r0 + grp*G_ + r;
            if (row < B_){
                int o = row*T_ + t;
                out[o]         = fminf(fmaxf(act,-5.4f),5.4f);
                out[BT_ + o]   = fatt;
                out[2*BT_ + o] = matt;
            }
            vv = fmaf(act, 0.1f, vv);
            xx = xx + vv*0.1f + act*0.005f;
            vx_s[grp][r][0] = vv; vx_s[grp][r][1] = xx;

            const float m0=sc_s[0],m1=sc_s[1],m2=sc_s[2],m3=sc_s[3],m4=sc_s[4],m5=sc_s[5];
            const float is0=sc_s[6],is1=sc_s[7],is2=sc_s[8],is3=sc_s[9],is4=sc_s[10],is5=sc_s[11];
            bool  men = (n10 > 0.5f);
            float edx = men ? (n5 - xx) : 70.0f;
            float edv = men ? (vv - n2) : 0.0f;
            extra_s[grp][r][0] = (vv - m0)*is0;
            extra_s[grp][r][1] = (n1 - m1)*is1;
            extra_s[grp][r][2] = ((vv - n1) - m2)*is2;
            extra_s[grp][r][3] = ((n4 - xx) - m3)*is3;
            extra_s[grp][r][4] = (edv - m4)*is4;
            extra_s[grp][r][5] = (edx - m5)*is5;
            extra_s[grp][r][6] = c0;
            extra_s[grp][r][7] = c1;
            extra_s[grp][r][8] = c2;
        }
        asm volatile("bar.sync 1, 256;" ::: "memory");
        build_h1(grp);   // h1 for next step
    };

    for (int t = 0; t < T_; t++){
        // even phase: half1 -> h2 group A(t);  half2 -> h3 + epilogue group B(t)
        if (half == 0) mlp2(0); else phase2(1, t);
        __syncthreads();
        // odd phase:  half1 -> h2 group B(t+1); half2 -> h3 + epilogue group A(t)
        if (half == 0) mlp2(1); else phase2(0, t);
        __syncthreads();
    }
}

extern "C" void kernel_launch(void* const* d_in, const int* in_sizes, int n_in,
                              void* d_out, int out_size) {
    (void)in_sizes; (void)n_in; (void)out_size;
    const float* idm_params = (const float*)d_in[0];
    const float* pb         = (const float*)d_in[1];
    const float* eh         = (const float*)d_in[2];
    const float* idm_s      = (const float*)d_in[3];
    const float* mcs        = (const float*)d_in[4];
    const float* W1         = (const float*)d_in[5];
    const float* b1         = (const float*)d_in[6];
    const float* W2         = (const float*)d_in[7];
    const float* b2         = (const float*)d_in[8];
    const float* W3         = (const float*)d_in[9];
    const float* b3         = (const float*)d_in[10];
    const float* Wf         = (const float*)d_in[11];
    const float* bf         = (const float*)d_in[12];
    const float* Wm         = (const float*)d_in[13];
    const float* bm         = (const float*)d_in[14];
    const float* smean      = (const float*)d_in[15];
    const float* svar       = (const float*)d_in[16];
    float* out = (float*)d_out;

    base1_kernel<<<B_/16, 128>>>(pb, eh, W1, b1);
    rollout_kernel<<<NCTA, 512>>>(idm_params, idm_s, mcs, W1, W2, b2, W3, b3,
                                  Wf, bf, Wm, bm, smean, svar, out);
}